// round 2
// baseline (speedup 1.0000x reference)
#include <cuda_runtime.h>
#include <cuda_bf16.h>
#include <math.h>

// 8192*8192 winner table: packed = ((pair_idx+1) << 3) | bucket, 0 = untouched.
// Zero-initialized at module load; self-cleaned by se_write_kernel each call so
// every graph replay sees it zeroed again (deterministic).
#define N_CELLS (64u * 1024u * 1024u)
__device__ int g_scratch[N_CELLS];

// Fused kernel: (a) election into g_scratch via fire-and-forget RED.MAX,
// (b) zero-fill of d_out with float4 stores. The two touch different buffers,
// so no synchronization is needed between them; the scattered atomics hide
// under the bandwidth-bound fill.
__global__ void se_fill_elect_kernel(const int* __restrict__ src,
                                     const int* __restrict__ dst,
                                     const int* __restrict__ path_len,
                                     int n_pairs, int nn, int max_path,
                                     float4* __restrict__ out4, int n4) {
    int tid = blockIdx.x * blockDim.x + threadIdx.x;
    int nth = gridDim.x * blockDim.x;

    // --- election (no-return atomicMax -> REDG.MAX, no latency stall) ---
    for (int i = tid; i < n_pairs; i += nth) {
        int pl = path_len[i];
        int bu = (pl < max_path ? pl : max_path) - 1;
        if (bu < 0) bu = 0;
        int packed = ((i + 1) << 3) | bu;
        long long cell = (long long)src[i] * nn + dst[i];
        atomicMax(&g_scratch[cell], packed);  // return value unused
    }

    // --- zero fill (the mandatory 256MB write) ---
    float4 z = make_float4(0.f, 0.f, 0.f, 0.f);
    for (int j = tid; j < n4; j += nth) {
        out4[j] = z;
    }
}

// Winner writes its bias value, then resets its scratch cell to 0 for the
// next replay. Exactly one winner per touched cell -> race-free stores.
// Losers may read 0 (post-reset) instead of the winner's packed value; both
// compare unequal to their own packed value, so the conclusion is unchanged.
__global__ void se_write_kernel(const float* __restrict__ b,
                                const int* __restrict__ src,
                                const int* __restrict__ dst,
                                const int* __restrict__ path_len,
                                int n_pairs, int nn, int max_path,
                                float* __restrict__ out_f) {
    int tid = blockIdx.x * blockDim.x + threadIdx.x;
    int nth = gridDim.x * blockDim.x;

    for (int i = tid; i < n_pairs; i += nth) {
        int pl = path_len[i];
        int bu = (pl < max_path ? pl : max_path) - 1;
        if (bu < 0) bu = 0;
        int packed = ((i + 1) << 3) | bu;
        long long cell = (long long)src[i] * nn + dst[i];
        int w = g_scratch[cell];
        if (w == packed) {
            out_f[cell] = __ldg(&b[bu]);
            g_scratch[cell] = 0;   // self-clean for next graph replay
        }
    }
}

extern "C" void kernel_launch(void* const* d_in, const int* in_sizes, int n_in,
                              void* d_out, int out_size) {
    // inputs: x [n_nodes,128] f32 (unused), b [max_path] f32,
    //         src [n_pairs] i32, dst [n_pairs] i32, path_len [n_pairs] i32
    const float* b        = (const float*)d_in[1];
    const int*   src      = (const int*)d_in[2];
    const int*   dst      = (const int*)d_in[3];
    const int*   path_len = (const int*)d_in[4];

    int max_path = in_sizes[1];
    int n_pairs  = in_sizes[2];
    int nn = (int)(sqrt((double)out_size) + 0.5);

    float*  out_f = (float*)d_out;
    float4* out4  = (float4*)d_out;
    int     n4    = out_size / 4;

    // Kernel 1: fused election + zero-fill. Grid sized for full-chip streaming.
    const int T = 256;
    int fill_blocks = 148 * 16;   // grid-stride; plenty of waves for BW
    se_fill_elect_kernel<<<fill_blocks, T>>>(src, dst, path_len,
                                             n_pairs, nn, max_path,
                                             out4, n4);

    // Kernel 2: winners write values, reset scratch.
    int blocks = (n_pairs + T - 1) / T;
    se_write_kernel<<<blocks, T>>>(b, src, dst, path_len,
                                   n_pairs, nn, max_path, out_f);
}

// round 3
// speedup vs baseline: 1.1803x; 1.1803x over previous
#include <cuda_runtime.h>
#include <cuda_bf16.h>
#include <math.h>

// 8192*8192 winner table: packed = ((pair_idx+1) << 3) | bucket, 0 = untouched.
// Zero-initialized at module load; the winner in se_write_kernel resets its
// cell to 0 each call, so every graph replay sees a zeroed table. In the
// timing loop the reset lines stay L2-resident (the fill uses evict-first
// stores), making the elect atomics L2 hits in steady state.
#define N_CELLS (64u * 1024u * 1024u)
__device__ int g_scratch[N_CELLS];

// Phase 1: election (runs BEFORE the fill so scratch stays hot in L2).
// Fire-and-forget atomicMax -> REDG.MAX, no return-value stall.
__global__ void se_elect_kernel(const int* __restrict__ src,
                                const int* __restrict__ dst,
                                const int* __restrict__ path_len,
                                int n_pairs, int nn, int max_path) {
    int i = blockIdx.x * blockDim.x + threadIdx.x;
    if (i >= n_pairs) return;
    int pl = path_len[i];
    int bu = (pl < max_path ? pl : max_path) - 1;
    if (bu < 0) bu = 0;
    int packed = ((i + 1) << 3) | bu;
    unsigned cell = (unsigned)src[i] * (unsigned)nn + (unsigned)dst[i];
    atomicMax(&g_scratch[cell], packed);
}

// Phase 2: 256MB zero-fill with evict-first streaming stores so the L2
// keeps the (small) dirty scratch working set resident for phase 3.
__global__ void se_fill_kernel(float4* __restrict__ out4, int n4) {
    int tid = blockIdx.x * blockDim.x + threadIdx.x;
    int nth = gridDim.x * blockDim.x;
    float4 z = make_float4(0.f, 0.f, 0.f, 0.f);
    for (int j = tid; j < n4; j += nth) {
        __stcs(&out4[j], z);
    }
}

// Phase 3: winner writes its bias value and resets its scratch cell.
// Exactly one winner per touched cell -> race-free. Losers reading the cell
// after the winner's reset see 0 != their packed value -> still losers.
__global__ void se_write_kernel(const float* __restrict__ b,
                                const int* __restrict__ src,
                                const int* __restrict__ dst,
                                const int* __restrict__ path_len,
                                int n_pairs, int nn, int max_path,
                                float* __restrict__ out_f) {
    int i = blockIdx.x * blockDim.x + threadIdx.x;
    if (i >= n_pairs) return;
    int pl = path_len[i];
    int bu = (pl < max_path ? pl : max_path) - 1;
    if (bu < 0) bu = 0;
    int packed = ((i + 1) << 3) | bu;
    unsigned cell = (unsigned)src[i] * (unsigned)nn + (unsigned)dst[i];
    int w = g_scratch[cell];
    if (w == packed) {
        out_f[cell] = __ldg(&b[bu]);
        g_scratch[cell] = 0;   // self-clean; stays dirty-resident in L2
    }
}

extern "C" void kernel_launch(void* const* d_in, const int* in_sizes, int n_in,
                              void* d_out, int out_size) {
    // inputs: x [n_nodes,128] f32 (unused), b [max_path] f32,
    //         src [n_pairs] i32, dst [n_pairs] i32, path_len [n_pairs] i32
    const float* b        = (const float*)d_in[1];
    const int*   src      = (const int*)d_in[2];
    const int*   dst      = (const int*)d_in[3];
    const int*   path_len = (const int*)d_in[4];

    int max_path = in_sizes[1];
    int n_pairs  = in_sizes[2];
    int nn = (int)(sqrt((double)out_size) + 0.5);

    float*  out_f = (float*)d_out;
    float4* out4  = (float4*)d_out;
    int     n4    = out_size / 4;

    const int T = 256;
    int pair_blocks = (n_pairs + T - 1) / T;

    // 1) elect winners into g_scratch (L2-hot in steady state)
    se_elect_kernel<<<pair_blocks, T>>>(src, dst, path_len,
                                        n_pairs, nn, max_path);

    // 2) bandwidth-bound zero fill (evict-first, preserves scratch in L2)
    int fill_blocks = 148 * 16;
    se_fill_kernel<<<fill_blocks, T>>>(out4, n4);

    // 3) winners write values, reset scratch
    se_write_kernel<<<pair_blocks, T>>>(b, src, dst, path_len,
                                        n_pairs, nn, max_path, out_f);
}